// round 17
// baseline (speedup 1.0000x reference)
#include <cuda_runtime.h>
#include <cuda_bf16.h>

// Problem constants: B=16, N=1024, M=4096, D=64
#define BB 16
#define NN 1024
#define MM 4096
#define DD 64
#define INF_BITS 0x7f800000u

// DTW partitioning: 8 CTAs per batch, 4 warps per CTA (1 warp per SMSP),
// each warp owns 128 columns (4 per lane).
#define DCTA 8
#define DW 4

// ---------------- device scratch (no cudaMalloc allowed) ----------------
__device__ float g_C[(size_t)BB * NN * MM];                 // 256 MB cost matrix
__device__ float g_x2[BB * NN];
__device__ float g_y2[BB * MM];
// packed moves: 4 cells per byte (2 bits each), row stride = MM/4 = 1024 bytes.
__device__ unsigned char g_mv[(size_t)BB * NN * (MM / 4) + 128];
// inter-CTA boundary handoff: 7 interfaces per batch, one word per row
__device__ unsigned g_bnd[BB][DCTA - 1][NN];
// per-CTA last-row argmin partials (8 CTAs per batch)
__device__ float g_pv[BB][DCTA];
__device__ int g_pi[BB][DCTA];

__device__ __forceinline__ unsigned ldcg_u32(const unsigned* p) {
    unsigned v;
    asm volatile("ld.global.cg.u32 %0, [%1];" : "=r"(v) : "l"(p));
    return v;
}
__device__ __forceinline__ void stcg_u32(unsigned* p, unsigned v) {
    asm volatile("st.global.cg.u32 [%0], %1;" :: "l"(p), "r"(v));
}
__device__ __forceinline__ void cpasync16(void* smem_dst, const void* gsrc) {
    unsigned saddr;
    asm("{ .reg .u64 t; cvta.to.shared.u64 t, %1; cvt.u32.u64 %0, t; }"
        : "=r"(saddr) : "l"(smem_dst));
    asm volatile("cp.async.cg.shared.global [%0], [%1], 16;"
                 :: "r"(saddr), "l"(gsrc) : "memory");
}
#define CP_COMMIT() asm volatile("cp.async.commit_group;" ::: "memory")
#define CP_WAIT6()  asm volatile("cp.async.wait_group 6;" ::: "memory")

// Packed f32x2 (Blackwell): two independent fp32 FMAs per instruction.
#define FMA_F32X2(d, a, b, c) \
    asm("fma.rn.f32x2 %0, %1, %2, %3;" : "=l"(d) : "l"(a), "l"(b), "l"(c))
#define PACK_F32X2(out, lo, hi) \
    asm("mov.b64 %0, {%1, %2};" : "=l"(out) : "r"(lo), "r"(hi))
#define UNPACK_F32X2(lo, hi, in) \
    asm("mov.b64 {%0, %1}, %2;" : "=r"(lo), "=r"(hi) : "l"(in))

// ---------------- kernel 0: row squared norms + boundary sentinel init ----------------
__global__ void norms_kernel(const float* __restrict__ x, const float* __restrict__ y) {
    int idx = blockIdx.x * blockDim.x + threadIdx.x;
    if (idx < BB * (DCTA - 1) * NN) ((unsigned*)g_bnd)[idx] = INF_BITS;
    const float* src;
    float* dst;
    if (idx < BB * NN) {
        src = x + (size_t)idx * DD;
        dst = g_x2 + idx;
    } else if (idx < BB * NN + BB * MM) {
        int k = idx - BB * NN;
        src = y + (size_t)k * DD;
        dst = g_y2 + k;
    } else {
        return;
    }
    float s = 0.f;
#pragma unroll
    for (int q = 0; q < DD / 4; q++) {
        float4 v = *(const float4*)(src + q * 4);
        s += v.x * v.x + v.y * v.y + v.z * v.z + v.w * v.w;
    }
    *dst = s;
}

// ---------------- kernel 1: C = x2 + y2 - 2 * x @ y^T (f32x2 packed FMA) ----------------
__global__ void __launch_bounds__(256, 2) gemm_kernel(const float* __restrict__ x,
                                                      const float* __restrict__ y) {
    __shared__ float Xs[32][128];
    __shared__ float Ys[32][128];
    int b = blockIdx.z;
    int i0 = blockIdx.y * 128;
    int j0 = blockIdx.x * 128;
    const float* xb = x + (size_t)b * NN * DD;
    const float* yb = y + (size_t)b * MM * DD;
    int tid = threadIdx.x;
    int txc = tid & 15, tyc = tid >> 4;

    unsigned long long acc2[8][4];
#pragma unroll
    for (int a = 0; a < 8; a++)
#pragma unroll
        for (int c = 0; c < 4; c++) acc2[a][c] = 0ull;

#pragma unroll
    for (int kt = 0; kt < DD; kt += 32) {
#pragma unroll
        for (int p = 0; p < 4; p++) {
            int idx = tid + p * 256;
            int q = idx & 7;
            int r = idx >> 3;
            float4 xv = *(const float4*)(xb + (size_t)(i0 + r) * DD + kt + q * 4);
            Xs[q * 4 + 0][r] = xv.x;
            Xs[q * 4 + 1][r] = xv.y;
            Xs[q * 4 + 2][r] = xv.z;
            Xs[q * 4 + 3][r] = xv.w;
            float4 yv = *(const float4*)(yb + (size_t)(j0 + r) * DD + kt + q * 4);
            Ys[q * 4 + 0][r] = yv.x;
            Ys[q * 4 + 1][r] = yv.y;
            Ys[q * 4 + 2][r] = yv.z;
            Ys[q * 4 + 3][r] = yv.w;
        }
        __syncthreads();
#pragma unroll
        for (int kk = 0; kk < 32; kk++) {
            float xf[8];
            *(float4*)&xf[0] = *(const float4*)&Xs[kk][tyc * 4];
            *(float4*)&xf[4] = *(const float4*)&Xs[kk][64 + tyc * 4];
            ulonglong2 ya = *(const ulonglong2*)&Ys[kk][txc * 4];
            ulonglong2 yb2 = *(const ulonglong2*)&Ys[kk][64 + txc * 4];
            unsigned long long yp0 = ya.x, yp1 = ya.y, yp2 = yb2.x, yp3 = yb2.y;
#pragma unroll
            for (int mm = 0; mm < 8; mm++) {
                unsigned long long xd;
                unsigned xb_ = __float_as_uint(xf[mm]);
                PACK_F32X2(xd, xb_, xb_);
                FMA_F32X2(acc2[mm][0], xd, yp0, acc2[mm][0]);
                FMA_F32X2(acc2[mm][1], xd, yp1, acc2[mm][1]);
                FMA_F32X2(acc2[mm][2], xd, yp2, acc2[mm][2]);
                FMA_F32X2(acc2[mm][3], xd, yp3, acc2[mm][3]);
            }
        }
        __syncthreads();
    }

    float y2v[8];
    *(float4*)&y2v[0] = *(const float4*)(g_y2 + b * MM + j0 + txc * 4);
    *(float4*)&y2v[4] = *(const float4*)(g_y2 + b * MM + j0 + 64 + txc * 4);
#pragma unroll
    for (int mm = 0; mm < 8; mm++) {
        int row = i0 + ((mm < 4) ? (tyc * 4 + mm) : (64 + tyc * 4 + mm - 4));
        float x2v = g_x2[b * NN + row];
        float* crow = g_C + ((size_t)b * NN + row) * MM + j0;
        float o[8];
#pragma unroll
        for (int q = 0; q < 4; q++) {
            unsigned lo, hi;
            UNPACK_F32X2(lo, hi, acc2[mm][q]);
            o[2 * q] = __uint_as_float(lo);
            o[2 * q + 1] = __uint_as_float(hi);
        }
        float4 v0, v1;
        v0.x = x2v + y2v[0] - 2.f * o[0];
        v0.y = x2v + y2v[1] - 2.f * o[1];
        v0.z = x2v + y2v[2] - 2.f * o[2];
        v0.w = x2v + y2v[3] - 2.f * o[3];
        v1.x = x2v + y2v[4] - 2.f * o[4];
        v1.y = x2v + y2v[5] - 2.f * o[5];
        v1.z = x2v + y2v[6] - 2.f * o[6];
        v1.w = x2v + y2v[7] - 2.f * o[7];
        *(float4*)(crow + txc * 4) = v0;
        *(float4*)(crow + 64 + txc * 4) = v1;
    }
}

// ---------------- kernel 2: dataflow subsequence-DTW forward DP ----------------
// 8 CTAs per batch, 4 warps/CTA (ONE warp per SMSP — no issue-slot sharing
// with spinning neighbors), warp owns 128 cols (4/lane, in regs). Same proven
// protocol as before: free-running warps, value-as-flag SPSC smem rings (INF
// sentinel, depth 128, producer back-pressure), chunk ownership reversed so
// dependencies flow high-wid -> low-wid, cp.async 6-deep C-row ring, eager
// inter-CTA gmem boundary loads.
__global__ void __launch_bounds__(32 * DW, 1) dtw_kernel() {
    const unsigned FULL = 0xffffffffu;
    const float INF = __uint_as_float(INF_BITS);
    int cta = blockIdx.x;
    int b = cta / DCTA, r = cta % DCTA;
    int t = threadIdx.x, lane = t & 31, w = t >> 5;   // w in [0, DW)
    int chunk = (DW - 1) - w;                   // 0 = leftmost chunk of this CTA
    int colbase = r * (MM / DCTA) + chunk * 128 + lane * 4;
    const float* Cp = g_C + (size_t)b * NN * MM + colbase;
    unsigned char* mvp = g_mv + (size_t)b * NN * (MM / 4) + (colbase >> 2);

    __shared__ volatile unsigned sB[DW - 1][128];  // sB[w]: written by warp w+1, read by warp w
    __shared__ float4 sring[DW][8][32];            // per-warp 8-deep C-row ring
    __shared__ float sRv[DW];
    __shared__ int sRi[DW];
    for (int q = t; q < (DW - 1) * 128; q += 32 * DW)
        ((volatile unsigned*)sB)[q] = INF_BITS;
    __syncthreads();

    const bool gin = (w == DW - 1 && r > 0);    // leftmost chunk consumes gmem boundary
    const bool gout = (w == 0 && r < DCTA - 1); // rightmost chunk produces gmem boundary
    const unsigned* gbi = gin ? &g_bnd[b][r - 1][0] : (const unsigned*)0;
    unsigned* gbo = gout ? &g_bnd[b][r][0] : (unsigned*)0;

    // ---- cp.async prologue: rows 0..5 in flight ----
#pragma unroll
    for (int k = 0; k < 6; k++) {
        cpasync16(&sring[w][k][lane], Cp + (size_t)k * MM);
        CP_COMMIT();
    }
    cpasync16(&sring[w][6][lane], Cp + 6 * (size_t)MM);
    CP_COMMIT();
    CP_WAIT6();

    // ---- row 0: D = C[0,:] ----
    float4 c4 = sring[w][0][lane];
    float pd[4] = {c4.x, c4.y, c4.z, c4.w};

    // acquire left boundary of row 0 (becomes prevB for row 1)
    float B = INF;
    if (w < DW - 1) {
        unsigned vb;
        do { vb = sB[w][0]; } while (vb == INF_BITS);
        if (lane == 0) sB[w][0] = INF_BITS;
        B = __uint_as_float(vb);
    } else if (gin) {
        unsigned vb;
        do { vb = ldcg_u32(gbi + 0); } while (vb == INF_BITS);
        B = __uint_as_float(vb);
    }
    float prevB = B;

    // publish D[0][chunk_end]
    {
        float dend = __shfl_sync(FULL, pd[3], 31);
        if (lane == 31) {
            unsigned ob = __float_as_uint(dend);
            if (w > 0) sB[w - 1][0] = ob;
            else if (gout) stcg_u32(gbo + 0, ob);
        }
    }

    for (int i = 1; i < NN; i++) {
        int q = i + 6;
        if (q < NN) cpasync16(&sring[w][q & 7][lane], Cp + (size_t)q * MM);
        CP_COMMIT();
        CP_WAIT6();                              // rows <= i ready

        // eager inter-CTA boundary load: latency overlaps the scan below
        unsigned vb0 = INF_BITS;
        if (gin && lane == 0) vb0 = ldcg_u32(gbi + i);

        float4 cc = sring[w][i & 7][lane];
        float c[4] = {cc.x, cc.y, cc.z, cc.w};

        // pl = D[i-1][j-1]
        float pl0 = __shfl_up_sync(FULL, pd[3], 1);
        if (lane == 0) pl0 = prevB;
        float a[4];
        a[0] = fminf(pd[0], pl0) + c[0];
#pragma unroll
        for (int k = 1; k < 4; k++) a[k] = fminf(pd[k], pd[k - 1]) + c[k];

        // thread-local min-plus compose
        float Sl = c[0], Ml = a[0];
#pragma unroll
        for (int k = 1; k < 4; k++) {
            Sl += c[k];
            Ml = fminf(Ml + c[k], a[k]);
        }
        // warp inclusive min-plus pair scan (speculative w.r.t. boundary B)
        float iS = Sl, iM = Ml;
#pragma unroll
        for (int off = 1; off < 32; off <<= 1) {
            float oS = __shfl_up_sync(FULL, iS, off);
            float oM = __shfl_up_sync(FULL, iM, off);
            if (lane >= off) { iM = fminf(oM + iS, iM); iS = oS + iS; }
        }
        float eS = __shfl_up_sync(FULL, iS, 1);
        float eM = __shfl_up_sync(FULL, iM, 1);
        if (lane == 0) { eS = 0.f; eM = INF; }

        // acquire left boundary B = D[i][chunk_start-1]
        B = INF;
        if (w < DW - 1) {
            unsigned vb;
            volatile unsigned* sl = &sB[w][i & 127];
            do { vb = *sl; } while (vb == INF_BITS);
            if (lane == 0) *sl = INF_BITS;
            B = __uint_as_float(vb);
        } else if (gin) {
            if (lane == 0) {
                while (vb0 == INF_BITS) vb0 = ldcg_u32(gbi + i);
            }
            vb0 = __shfl_sync(FULL, vb0, 0);
            B = __uint_as_float(vb0);
        }

        // publish own boundary ASAP (lane 31 holds the chunk totals).
        if (lane == 31) {
            float dend = fminf(B + iS, iM);
            unsigned ob = __float_as_uint(dend);
            if (w > 0) {
                volatile unsigned* so = &sB[w - 1][i & 127];
                while (*so != INF_BITS) {}       // back-pressure (depth-128 ring)
                *so = ob;
            } else if (gout) {
                stcg_u32(gbo + i, ob);
            }
        }

        // finalize with the carry applied
        float M_ex = fminf(B + eS, eM);         // == D[i][lane_start-1]
        float nd[4];
        float Mr = M_ex;
#pragma unroll
        for (int k = 0; k < 4; k++) {
            Mr = fminf(Mr + c[k], a[k]);
            nd[k] = Mr;
        }
        // move codes (dd = D[i-1][j-1], du = D[i-1][j], dl = D[i][j-1])
        unsigned pk = 0;
        float dl = M_ex, dd = pl0;
#pragma unroll
        for (int k = 0; k < 4; k++) {
            float du = pd[k];
            unsigned m = (du <= dl) ? 1u : 2u;
            if (dd <= du && dd <= dl) m = 0u;
            pk |= m << (2 * k);
            dd = du;
            dl = nd[k];
        }
        mvp[(size_t)i * (MM / 4)] = (unsigned char)pk;

        prevB = B;
#pragma unroll
        for (int k = 0; k < 4; k++) pd[k] = nd[k];
    }

    // ---- per-CTA argmin of last row (first index on exact ties) ----
    float bv = pd[0];
    int bi = colbase;
#pragma unroll
    for (int k = 1; k < 4; k++)
        if (pd[k] < bv) { bv = pd[k]; bi = colbase + k; }
#pragma unroll
    for (int off = 16; off > 0; off >>= 1) {
        float ov = __shfl_down_sync(FULL, bv, off);
        int oi = __shfl_down_sync(FULL, bi, off);
        if (ov < bv || (ov == bv && oi < bi)) { bv = ov; bi = oi; }
    }
    if (lane == 0) { sRv[w] = bv; sRi[w] = bi; }
    __syncthreads();
    if (t == 0) {
        float v = sRv[0]; int ix = sRi[0];
#pragma unroll
        for (int qq = 1; qq < DW; qq++)
            if (sRv[qq] < v || (sRv[qq] == v && sRi[qq] < ix)) { v = sRv[qq]; ix = sRi[qq]; }
        g_pv[b][r] = v;
        g_pi[b][r] = ix;
    }
}

// ---------------- kernel 3: backtrack over packed moves ----------------
// One warp per batch. The 64-row x 20-word window is stored TRANSPOSED in
// smem (tileT[wcol][row]) so consecutive rows at the same word-column are
// contiguous: one LDS.128 yields the move-words of 4 rows, replacing the
// per-row dependent LDS with a register 4-way select. Left-runs decode
// in-register as before.
__global__ void __launch_bounds__(32) backtrack_kernel(const float* __restrict__ xt,
                                                       const float* __restrict__ yt,
                                                       float* __restrict__ out) {
    int b = blockIdx.x;
    int lane = threadIdx.x;
    __shared__ unsigned tileT[20][64];   // [wcol][row], 256B per wcol (16B aligned)
    __shared__ int syl[NN];
    __shared__ int sij[2];
    const unsigned char* mvb = g_mv + (size_t)b * NN * (MM / 4);

    // final argmin across the 8 CTA partials (first global index on ties)
    if (lane == 0) {
        float bv = g_pv[b][0]; int bi = g_pi[b][0];
#pragma unroll
        for (int q = 1; q < DCTA; q++) {
            float v = g_pv[b][q]; int ix = g_pi[b][q];
            if (v < bv || (v == bv && ix < bi)) { bv = v; bi = ix; }
        }
        out[b] = bv;                  // dtw_cost
        syl[NN - 1] = bi;
        sij[0] = NN - 1; sij[1] = bi;
    }
    __syncwarp();
    int i = sij[0], j = sij[1];

    while (i > 0) {
        int r0 = i - 63; if (r0 < 1) r0 = 1;
        int wb0 = (j >> 4) - 15; if (wb0 < 0) wb0 = 0;
        wb0 &= ~3;                    // 16B-align the word window
        // cooperative transposed load: rows r0..r0+63, words wb0..wb0+19
#pragma unroll
        for (int p = 0; p < 10; p++) {
            int idx = lane + p * 32;  // 0..319
            int rr = idx / 5, q = idx - rr * 5;
            uint4 v = *(const uint4*)(mvb + (size_t)(r0 + rr) * (MM / 4) + wb0 * 4 + q * 16);
            tileT[4 * q + 0][rr] = v.x;
            tileT[4 * q + 1][rr] = v.y;
            tileT[4 * q + 2][rr] = v.z;
            tileT[4 * q + 3][rr] = v.w;
        }
        __syncwarp();
        if (lane == 0) {
            int trow = i - r0;                     // in [0, 63]
            int wcol = (j >> 4) - wb0;             // in [0, 19]
            int gb = trow & ~3;
            uint4 g = *(const uint4*)&tileT[wcol][gb];
            while (i > 0 && trow >= 0 && wcol >= 0) {
                int s = trow - gb;
                unsigned word = (s == 0) ? g.x : (s == 1) ? g.y : (s == 2) ? g.z : g.w;
                unsigned mv = (word >> ((j & 15) * 2)) & 3u;
                if (mv == 2u) {                    // left
                    j--;
                    if ((j & 15) == 15) {          // crossed word boundary
                        wcol--;
                        if (wcol < 0) break;
                        g = *(const uint4*)&tileT[wcol][gb];
                    }
                } else {                           // diag (0) or up (1)
                    i--;
                    trow--;
                    j -= (mv == 0u);
                    syl[i] = j;
                    bool cross = (mv == 0u) && ((j & 15) == 15);
                    if (trow < 0) break;           // window exhausted (reload)
                    if (cross) {
                        wcol--;
                        if (wcol < 0) break;
                        gb = trow & ~3;
                        g = *(const uint4*)&tileT[wcol][gb];
                    } else if (trow < gb) {
                        gb -= 4;
                        g = *(const uint4*)&tileT[wcol][gb];
                    }
                }
            }
            sij[0] = i; sij[1] = j;
        }
        __syncwarp();
        i = sij[0]; j = sij[1];
        __syncwarp();
    }

    // write w_ts (= x_t) and w_vs (= y_t gathered at per-row path column)
    for (int n = lane; n < NN; n += 32) {
        out[BB + b * NN + n] = xt[b * NN + n];
        out[BB + BB * NN + b * NN + n] = yt[(size_t)b * MM + syl[n]];
    }
}

// ---------------- launch ----------------
extern "C" void kernel_launch(void* const* d_in, const int* in_sizes, int n_in,
                              void* d_out, int out_size) {
    const float* x = (const float*)d_in[0];   // [16,1024,64]
    const float* y = (const float*)d_in[1];   // [16,4096,64]
    const float* xt = (const float*)d_in[2];  // [16,1024]
    const float* yt = (const float*)d_in[3];  // [16,4096]
    float* out = (float*)d_out;               // [16] cost, [16,1024] w_ts, [16,1024] w_vs

    // covers both norms (BB*NN + BB*MM = 81920) and bnd init (BB*7*NN = 114688)
    int nInit = BB * (DCTA - 1) * NN;
    if (nInit < BB * NN + BB * MM) nInit = BB * NN + BB * MM;
    norms_kernel<<<(nInit + 255) / 256, 256>>>(x, y);

    dim3 gg(MM / 128, NN / 128, BB);
    gemm_kernel<<<gg, 256>>>(x, y);

    dtw_kernel<<<BB * DCTA, 32 * DW>>>();

    backtrack_kernel<<<BB, 32>>>(xt, yt, out);
}